// round 5
// baseline (speedup 1.0000x reference)
#include <cuda_runtime.h>
#include <cuda_bf16.h>
#include <cstdint>
#include <math.h>

// Problem constants
#define BB 2048
#define DD 4096
#define PP 64
#define EE 8
#define KK 64
#define TWO_C 128

#define WROW 72          // padded row stride in bf16 (144 B): conflict-free ldmatrix
#define WROWB 144

// persistent accumulators for in-kernel loss (self-resetting each launch)
__device__ unsigned long long g_lsum[EE];   // sum_b select[b,e], fixed point 2^32
__device__ int                g_cnt[EE];    // count of b routed to e
__device__ unsigned int       g_ticket;

// ---------------- helpers ----------------
__device__ __forceinline__ uint32_t smem_u32(const void* p) {
    uint32_t a;
    asm("{ .reg .u64 t; cvta.to.shared.u64 t, %1; cvt.u32.u64 %0, t; }" : "=r"(a) : "l"(p));
    return a;
}

__device__ __forceinline__ void ldsm_x4(uint32_t& r0, uint32_t& r1, uint32_t& r2, uint32_t& r3,
                                        uint32_t addr) {
    asm volatile("ldmatrix.sync.aligned.m8n8.x4.shared.b16 {%0,%1,%2,%3}, [%4];"
                 : "=r"(r0), "=r"(r1), "=r"(r2), "=r"(r3) : "r"(addr));
}

__device__ __forceinline__ void mma_bf16(float* d, const uint32_t* a, uint32_t b0, uint32_t b1) {
    asm volatile(
        "mma.sync.aligned.m16n8k16.row.col.f32.bf16.bf16.f32 "
        "{%0,%1,%2,%3}, {%4,%5,%6,%7}, {%8,%9}, {%0,%1,%2,%3};"
        : "+f"(d[0]), "+f"(d[1]), "+f"(d[2]), "+f"(d[3])
        : "r"(a[0]), "r"(a[1]), "r"(a[2]), "r"(a[3]), "r"(b0), "r"(b1));
}

__device__ __forceinline__ uint32_t pack_bf16x2(float lo, float hi) {
    __nv_bfloat162 h = __float22bfloat162_rn(make_float2(lo, hi));
    return *(uint32_t*)&h;
}

// ---------------------------------------------------------------------------
// Single fused kernel: one block per batch element, 256 threads (8 warps).
//   router exact fp32 (single-warp shuffle), bf16 HMMA expert GEMM,
//   fp32 cube epilogue, in-kernel deterministic loss via fixed-point atomics.
// ---------------------------------------------------------------------------
__global__ __launch_bounds__(256, 3) void moe_fused(
    const float* __restrict__ x,
    const float* __restrict__ rw,
    const float* __restrict__ ew,
    const float* __restrict__ eb,
    float* __restrict__ out,
    int full)
{
    __shared__ __align__(16) __nv_bfloat16 asm_w[TWO_C * WROW];  // A: weights [c][k]
    __shared__ __align__(16) __nv_bfloat16 bsm_x[PP * WROW];     // B: x patches [p][k]
    __shared__ float bias_s[TWO_C];
    __shared__ float wred[8];
    __shared__ int   s_idx;
    __shared__ float s_gate;

    const int b = blockIdx.x;
    const int t = threadIdx.x;
    const int wid = t >> 5, lid = t & 31;
    const float* xb = x + (size_t)b * DD;
    float* xpf = reinterpret_cast<float*>(asm_w);    // 32x64 fp32 partials (aliased; dead before weights)

    // ---- x load: thread owns k8=(t&7)*8, rows p=(t>>3)+32q; float4 in, uint4 bf16 out
    const int k8 = (t & 7) << 3;
    const int pg = t >> 3;
    float kacc[8];
    #pragma unroll
    for (int i = 0; i < 8; i++) kacc[i] = 0.f;

    #pragma unroll
    for (int q = 0; q < 2; q++) {
        const int p = pg + (q << 5);
        const float4* xp = (const float4*)(xb + p * KK + k8);
        float4 v0 = xp[0], v1 = xp[1];
        kacc[0] += v0.x; kacc[1] += v0.y; kacc[2] += v0.z; kacc[3] += v0.w;
        kacc[4] += v1.x; kacc[5] += v1.y; kacc[6] += v1.z; kacc[7] += v1.w;
        uint4 pk;
        pk.x = pack_bf16x2(v0.x, v0.y);
        pk.y = pack_bf16x2(v0.z, v0.w);
        pk.z = pack_bf16x2(v1.x, v1.y);
        pk.w = pack_bf16x2(v1.z, v1.w);
        *(uint4*)&bsm_x[p * WROW + k8] = pk;
    }
    *(float4*)&xpf[pg * KK + k8]     = make_float4(kacc[0], kacc[1], kacc[2], kacc[3]);
    *(float4*)&xpf[pg * KK + k8 + 4] = make_float4(kacc[4], kacc[5], kacc[6], kacc[7]);
    __syncthreads();                                   // (1) B tile + partials ready

    // ---- single-warp router (exact fp32)
    if (wid == 0) {
        float xa = 0.f, xb2 = 0.f;
        #pragma unroll
        for (int g = 0; g < 32; g++) {
            xa  += xpf[g * KK + lid];
            xb2 += xpf[g * KK + 32 + lid];
        }
        float part[EE];
        #pragma unroll
        for (int e = 0; e < EE; e++)
            part[e] = xa * rw[e * KK + lid] + xb2 * rw[e * KK + 32 + lid];
        #pragma unroll
        for (int o = 16; o > 0; o >>= 1)
            #pragma unroll
            for (int e = 0; e < EE; e++)
                part[e] += __shfl_xor_sync(0xffffffffu, part[e], o);

        float g = part[0]; int idx = 0;
        #pragma unroll
        for (int e = 1; e < EE; e++) { if (part[e] > g) { g = part[e]; idx = e; } }

        if (lid == 0) {
            s_idx = idx; s_gate = g;
            // loss accumulation (fixed point 2^32, deterministic)
            #pragma unroll
            for (int e = 0; e < EE; e++) {
                long long q = llrint((double)part[e] * 4294967296.0);
                atomicAdd(&g_lsum[e], (unsigned long long)q);
            }
            atomicAdd(&g_cnt[idx], 1);
            __threadfence();
            unsigned int tk = atomicAdd(&g_ticket, 1u);
            if (tk == BB - 1) {                        // last block: finish loss, reset state
                __threadfence();
                double L = 0.0;
                #pragma unroll
                for (int e = 0; e < EE; e++) {
                    unsigned long long sraw = atomicAdd(&g_lsum[e], 0ULL);
                    int cc = atomicAdd(&g_cnt[e], 0);
                    L += ((double)(long long)sraw * (1.0 / 4294967296.0)) * (double)cc;
                }
                if (full)
                    out[BB * 2 + BB * EE] =
                        (float)(L * (double)EE / ((double)BB * (double)BB));
                #pragma unroll
                for (int e = 0; e < EE; e++) {
                    atomicExch(&g_lsum[e], 0ULL);
                    atomicExch(&g_cnt[e], 0);
                }
                atomicExch(&g_ticket, 0u);
            }
        }
    }
    __syncthreads();                                   // (2) routing decided; xpf dead

    const int   eidx = s_idx;
    const float gate = s_gate;

    if (full && t < EE)
        out[BB * 2 + b * EE + t] = (t == eidx && gate != 0.f) ? 1.f : 0.f;

    // ---- stage selected expert's weights: fp32 L2 read -> bf16 smem (inline convert)
    {
        const float4* src = (const float4*)(ew + (size_t)eidx * (TWO_C * KK));
        #pragma unroll
        for (int i = 0; i < 8; i++) {
            int idx4 = (i << 8) + t;                   // 0..2047; row = idx4>>4, ch = idx4&15
            float4 v = src[idx4];
            uint2 pk;
            pk.x = pack_bf16x2(v.x, v.y);
            pk.y = pack_bf16x2(v.z, v.w);
            *(uint2*)&asm_w[(idx4 >> 4) * WROW + ((idx4 & 15) << 2)] = pk;
        }
    }
    if (t < TWO_C) bias_s[t] = eb[eidx * TWO_C + t];
    __syncthreads();                                   // (3) A tile ready

    // ---- GEMM: warp grid 4c x 2p; warp tile 32c x 32p
    const int cw = wid & 3;
    const int pw = wid >> 2;
    const uint32_t Abase = smem_u32(asm_w);
    const uint32_t Bbase = smem_u32(bsm_x);

    const uint32_t a_addr = Abase + (uint32_t)(((cw << 5) + (lid & 15)) * WROWB + ((lid >> 4) << 4));
    const uint32_t b_addr = Bbase + (uint32_t)(((pw << 5) + (lid & 7) + ((lid >> 4) << 3)) * WROWB
                                               + (((lid >> 3) & 1) << 4));

    float accv[2][4][4];
    #pragma unroll
    for (int m = 0; m < 2; m++)
        #pragma unroll
        for (int n = 0; n < 4; n++)
            #pragma unroll
            for (int i = 0; i < 4; i++) accv[m][n][i] = 0.f;

    #pragma unroll
    for (int ks = 0; ks < 4; ks++) {
        uint32_t a0[4], a1[4];
        ldsm_x4(a0[0], a0[1], a0[2], a0[3], a_addr + ks * 32);
        ldsm_x4(a1[0], a1[1], a1[2], a1[3], a_addr + 16 * WROWB + ks * 32);
        #pragma unroll
        for (int j = 0; j < 2; j++) {
            uint32_t r0, r1, r2, r3;
            ldsm_x4(r0, r1, r2, r3, b_addr + j * (16 * WROWB) + ks * 32);
            mma_bf16(accv[0][2 * j],     a0, r0, r1);
            mma_bf16(accv[0][2 * j + 1], a0, r2, r3);
            mma_bf16(accv[1][2 * j],     a1, r0, r1);
            mma_bf16(accv[1][2 * j + 1], a1, r2, r3);
        }
    }

    // ---- epilogue: z = d + bias[c]; sum z^3 over all p of this warp
    float part = 0.f;
    #pragma unroll
    for (int m = 0; m < 2; m++) {
        const float bv1 = bias_s[(cw << 5) + (m << 4) + (lid >> 2)];
        const float bv2 = bias_s[(cw << 5) + (m << 4) + (lid >> 2) + 8];
        #pragma unroll
        for (int n = 0; n < 4; n++) {
            float z0 = accv[m][n][0] + bv1;
            float z1 = accv[m][n][1] + bv1;
            float z2 = accv[m][n][2] + bv2;
            float z3 = accv[m][n][3] + bv2;
            part += z0 * z0 * z0 + z1 * z1 * z1 + z2 * z2 * z2 + z3 * z3 * z3;
        }
    }
    #pragma unroll
    for (int o = 16; o > 0; o >>= 1)
        part += __shfl_xor_sync(0xffffffffu, part, o);
    if (lid == 0) wred[wid] = part;
    __syncthreads();                                   // (4)

    if (t == 0) {
        // cw in {0,1} -> c<64 : warps 0,1,4,5 ; cw in {2,3} -> c>=64 : warps 2,3,6,7
        float v0 = wred[0] + wred[1] + wred[4] + wred[5];
        float v1 = wred[2] + wred[3] + wred[6] + wred[7];
        float a0 = gate * v0, a1 = gate * v1;
        float m  = fmaxf(a0, a1);
        float e0 = expf(a0 - m), e1 = expf(a1 - m);
        float inv = 1.f / (e0 + e1);
        out[b * 2 + 0] = e0 * inv;
        out[b * 2 + 1] = e1 * inv;
    }
}

// ---------------------------------------------------------------------------
extern "C" void kernel_launch(void* const* d_in, const int* in_sizes, int n_in,
                              void* d_out, int out_size)
{
    const float* x  = (const float*)d_in[0];
    const float* rw = (const float*)d_in[1];
    const float* ew = (const float*)d_in[2];
    const float* eb = (const float*)d_in[3];
    float* out = (float*)d_out;

    const int full = (out_size >= BB * 2 + BB * EE + 1) ? 1 : 0;

    moe_fused<<<BB, 256>>>(x, rw, ew, eb, out, full);
}

// round 6
// speedup vs baseline: 1.1405x; 1.1405x over previous
#include <cuda_runtime.h>
#include <cuda_bf16.h>
#include <cstdint>
#include <math.h>

// Problem constants
#define BB 2048
#define DD 4096
#define PP 64
#define EE 8
#define KK 64
#define TWO_C 128

#define WROW 72          // padded row stride in bf16 (144 B): conflict-free ldmatrix
#define WROWB 144

#define TASKS_PER_BLOCK 4
#define NBLK (BB / TASKS_PER_BLOCK)   // 512

// inter-kernel scratch
__device__ float g_select[BB * EE];
__device__ float g_gate[BB];
__device__ int   g_index[BB];
__device__ int   g_order[BB];         // b's sorted by expert

// ---------------- helpers ----------------
__device__ __forceinline__ uint32_t smem_u32(const void* p) {
    uint32_t a;
    asm("{ .reg .u64 t; cvta.to.shared.u64 t, %1; cvt.u32.u64 %0, t; }" : "=r"(a) : "l"(p));
    return a;
}

__device__ __forceinline__ void ldsm_x4(uint32_t& r0, uint32_t& r1, uint32_t& r2, uint32_t& r3,
                                        uint32_t addr) {
    asm volatile("ldmatrix.sync.aligned.m8n8.x4.shared.b16 {%0,%1,%2,%3}, [%4];"
                 : "=r"(r0), "=r"(r1), "=r"(r2), "=r"(r3) : "r"(addr));
}

__device__ __forceinline__ void mma_bf16(float* d, const uint32_t* a, uint32_t b0, uint32_t b1) {
    asm volatile(
        "mma.sync.aligned.m16n8k16.row.col.f32.bf16.bf16.f32 "
        "{%0,%1,%2,%3}, {%4,%5,%6,%7}, {%8,%9}, {%0,%1,%2,%3};"
        : "+f"(d[0]), "+f"(d[1]), "+f"(d[2]), "+f"(d[3])
        : "r"(a[0]), "r"(a[1]), "r"(a[2]), "r"(a[3]), "r"(b0), "r"(b1));
}

__device__ __forceinline__ uint32_t pack_bf16x2(float lo, float hi) {
    __nv_bfloat162 h = __float22bfloat162_rn(make_float2(lo, hi));
    return *(uint32_t*)&h;
}

// ---------------------------------------------------------------------------
// K1: router. One warp per batch element; exact fp32 entirely in registers.
// ---------------------------------------------------------------------------
__global__ __launch_bounds__(256) void router_kernel(
    const float* __restrict__ x,
    const float* __restrict__ rw,
    float* __restrict__ out,
    int full)
{
    const int wid = threadIdx.x >> 5, lid = threadIdx.x & 31;
    const int b = blockIdx.x * 8 + wid;
    const float4* xb4 = (const float4*)(x + (size_t)b * DD);

    // per-lane k-group sums: lane l accumulates k = 4*(l&15) .. +3
    float4 acc = make_float4(0.f, 0.f, 0.f, 0.f);
    #pragma unroll
    for (int j = 0; j < 32; j++) {
        float4 v = xb4[lid + (j << 5)];
        acc.x += v.x; acc.y += v.y; acc.z += v.z; acc.w += v.w;
    }
    acc.x += __shfl_xor_sync(0xffffffffu, acc.x, 16);
    acc.y += __shfl_xor_sync(0xffffffffu, acc.y, 16);
    acc.z += __shfl_xor_sync(0xffffffffu, acc.z, 16);
    acc.w += __shfl_xor_sync(0xffffffffu, acc.w, 16);
    // now every lane holds xs4 of k-group (lid & 15), duplicated across halves

    const float4* rw4 = (const float4*)rw;
    float sel[EE];
    #pragma unroll
    for (int e = 0; e < EE; e++) {
        float4 w = rw4[e * 16 + (lid & 15)];
        float p = acc.x * w.x + acc.y * w.y + acc.z * w.z + acc.w * w.w;
        p += __shfl_xor_sync(0xffffffffu, p, 8);
        p += __shfl_xor_sync(0xffffffffu, p, 4);
        p += __shfl_xor_sync(0xffffffffu, p, 2);
        p += __shfl_xor_sync(0xffffffffu, p, 1);
        sel[e] = p;                         // valid on all lanes
    }

    float g = sel[0]; int idx = 0;
    #pragma unroll
    for (int e = 1; e < EE; e++) { if (sel[e] > g) { g = sel[e]; idx = e; } }

    if (lid == 0) {
        g_index[b] = idx;
        g_gate[b]  = g;
        float4* s4 = (float4*)(g_select + b * EE);
        s4[0] = make_float4(sel[0], sel[1], sel[2], sel[3]);
        s4[1] = make_float4(sel[4], sel[5], sel[6], sel[7]);
    }
    if (full && lid < EE)
        out[BB * 2 + b * EE + lid] = (lid == idx && g != 0.f) ? 1.f : 0.f;
}

// ---------------------------------------------------------------------------
// K2: compaction (expert-sorted order) + exact loss. Single block.
// ---------------------------------------------------------------------------
__global__ __launch_bounds__(1024) void compact_kernel(float* __restrict__ out, int full)
{
    __shared__ int hist[EE];
    __shared__ int ofs[EE];
    __shared__ float esum[32][EE];

    const int t = threadIdx.x;
    if (t < EE) hist[t] = 0;
    __syncthreads();

    int myidx[2];
    #pragma unroll
    for (int i = 0; i < 2; i++) {
        myidx[i] = g_index[t + (i << 10)];
        atomicAdd(&hist[myidx[i]], 1);
    }
    __syncthreads();

    if (t == 0) {
        int run = 0;
        #pragma unroll
        for (int e = 0; e < EE; e++) { ofs[e] = run; run += hist[e]; }
    }
    __syncthreads();

    #pragma unroll
    for (int i = 0; i < 2; i++) {
        int pos = atomicAdd(&ofs[myidx[i]], 1);
        g_order[pos] = t + (i << 10);
    }

    // ---- loss: S_e = sum_b select[b,e]; loss = E/B^2 * sum_e S_e * cnt_e
    float my[EE];
    #pragma unroll
    for (int e = 0; e < EE; e++) my[e] = 0.f;
    #pragma unroll
    for (int i = 0; i < 2; i++) {
        const float4* s4 = (const float4*)(g_select + (t + (i << 10)) * EE);
        float4 v0 = s4[0], v1 = s4[1];
        my[0] += v0.x; my[1] += v0.y; my[2] += v0.z; my[3] += v0.w;
        my[4] += v1.x; my[5] += v1.y; my[6] += v1.z; my[7] += v1.w;
    }
    #pragma unroll
    for (int o = 16; o > 0; o >>= 1)
        #pragma unroll
        for (int e = 0; e < EE; e++)
            my[e] += __shfl_xor_sync(0xffffffffu, my[e], o);

    const int wid = t >> 5, lid = t & 31;
    if (lid == 0) {
        #pragma unroll
        for (int e = 0; e < EE; e++) esum[wid][e] = my[e];
    }
    __syncthreads();

    if (t == 0 && full) {
        float L = 0.f;
        #pragma unroll
        for (int e = 0; e < EE; e++) {
            float S = 0.f;
            #pragma unroll
            for (int w = 0; w < 32; w++) S += esum[w][e];
            L += S * (float)hist[e];
        }
        out[BB * 2 + BB * EE] = L * (float)EE / ((float)BB * (float)BB);
    }
}

// ---------------------------------------------------------------------------
// K3: expert GEMMs. Block handles TASKS_PER_BLOCK consecutive expert-sorted
// tasks; weights staged once per block (re-staged only at expert boundaries).
// ---------------------------------------------------------------------------
__global__ __launch_bounds__(256, 3) void expert_kernel(
    const float* __restrict__ x,
    const float* __restrict__ ew,
    const float* __restrict__ eb,
    float* __restrict__ out)
{
    __shared__ __align__(16) __nv_bfloat16 asm_w[TWO_C * WROW];  // A: weights [c][k]
    __shared__ __align__(16) __nv_bfloat16 bsm_x[PP * WROW];     // B: x patches [p][k]
    __shared__ float bias_s[TWO_C];
    __shared__ float wred[8];

    const int t = threadIdx.x;
    const int wid = t >> 5, lid = t & 31;
    const int cw = wid & 3;
    const int pw = wid >> 2;
    const uint32_t Abase = smem_u32(asm_w);
    const uint32_t Bbase = smem_u32(bsm_x);
    const uint32_t a_addr = Abase + (uint32_t)(((cw << 5) + (lid & 15)) * WROWB + ((lid >> 4) << 4));
    const uint32_t b_addr = Bbase + (uint32_t)(((pw << 5) + (lid & 7) + ((lid >> 4) << 3)) * WROWB
                                               + (((lid >> 3) & 1) << 4));
    const int k8 = (t & 7) << 3;
    const int pg = t >> 3;

    int e_cur = -1;

    for (int it = 0; it < TASKS_PER_BLOCK; it++) {
        const int task = blockIdx.x * TASKS_PER_BLOCK + it;
        const int b    = __ldg(&g_order[task]);
        const int e    = __ldg(&g_index[b]);

        // ---- stage weights on expert change (fp32 L2 -> bf16 smem)
        if (e != e_cur) {
            e_cur = e;
            const float4* src = (const float4*)(ew + (size_t)e * (TWO_C * KK));
            #pragma unroll
            for (int i = 0; i < 8; i++) {
                int idx4 = (i << 8) + t;               // row = idx4>>4, ch = idx4&15
                float4 v = src[idx4];
                uint2 pk;
                pk.x = pack_bf16x2(v.x, v.y);
                pk.y = pack_bf16x2(v.z, v.w);
                *(uint2*)&asm_w[(idx4 >> 4) * WROW + ((idx4 & 15) << 2)] = pk;
            }
            if (t < TWO_C) bias_s[t] = eb[e * TWO_C + t];
        }

        // ---- stage x[b] (fp32 -> bf16 smem)
        {
            const float* xb = x + (size_t)b * DD;
            #pragma unroll
            for (int q = 0; q < 2; q++) {
                const int p = pg + (q << 5);
                const float4* xp = (const float4*)(xb + p * KK + k8);
                float4 v0 = xp[0], v1 = xp[1];
                uint4 pk;
                pk.x = pack_bf16x2(v0.x, v0.y);
                pk.y = pack_bf16x2(v0.z, v0.w);
                pk.z = pack_bf16x2(v1.x, v1.y);
                pk.w = pack_bf16x2(v1.z, v1.w);
                *(uint4*)&bsm_x[p * WROW + k8] = pk;
            }
        }
        __syncthreads();                               // tiles ready

        // ---- GEMM: warp grid 4c x 2p; warp tile 32c x 32p
        float accv[2][4][4];
        #pragma unroll
        for (int m = 0; m < 2; m++)
            #pragma unroll
            for (int n = 0; n < 4; n++)
                #pragma unroll
                for (int i = 0; i < 4; i++) accv[m][n][i] = 0.f;

        #pragma unroll
        for (int ks = 0; ks < 4; ks++) {
            uint32_t a0[4], a1[4];
            ldsm_x4(a0[0], a0[1], a0[2], a0[3], a_addr + ks * 32);
            ldsm_x4(a1[0], a1[1], a1[2], a1[3], a_addr + 16 * WROWB + ks * 32);
            #pragma unroll
            for (int j = 0; j < 2; j++) {
                uint32_t r0, r1, r2, r3;
                ldsm_x4(r0, r1, r2, r3, b_addr + j * (16 * WROWB) + ks * 32);
                mma_bf16(accv[0][2 * j],     a0, r0, r1);
                mma_bf16(accv[0][2 * j + 1], a0, r2, r3);
                mma_bf16(accv[1][2 * j],     a1, r0, r1);
                mma_bf16(accv[1][2 * j + 1], a1, r2, r3);
            }
        }

        // ---- epilogue: z = d + bias[c]; sum z^3
        float part = 0.f;
        #pragma unroll
        for (int m = 0; m < 2; m++) {
            const float bv1 = bias_s[(cw << 5) + (m << 4) + (lid >> 2)];
            const float bv2 = bias_s[(cw << 5) + (m << 4) + (lid >> 2) + 8];
            #pragma unroll
            for (int n = 0; n < 4; n++) {
                float z0 = accv[m][n][0] + bv1;
                float z1 = accv[m][n][1] + bv1;
                float z2 = accv[m][n][2] + bv2;
                float z3 = accv[m][n][3] + bv2;
                part += z0 * z0 * z0 + z1 * z1 * z1 + z2 * z2 * z2 + z3 * z3 * z3;
            }
        }
        #pragma unroll
        for (int o = 16; o > 0; o >>= 1)
            part += __shfl_xor_sync(0xffffffffu, part, o);
        if (lid == 0) wred[wid] = part;
        __syncthreads();                               // also protects bsm/asm reuse

        if (t == 0) {
            float v0 = wred[0] + wred[1] + wred[4] + wred[5];   // c in [0,64)
            float v1 = wred[2] + wred[3] + wred[6] + wred[7];   // c in [64,128)
            float gate = __ldg(&g_gate[b]);
            float a0 = gate * v0, a1 = gate * v1;
            float m  = fmaxf(a0, a1);
            float e0 = expf(a0 - m), e1 = expf(a1 - m);
            float inv = 1.f / (e0 + e1);
            out[b * 2 + 0] = e0 * inv;
            out[b * 2 + 1] = e1 * inv;
        }
    }
}

// ---------------------------------------------------------------------------
extern "C" void kernel_launch(void* const* d_in, const int* in_sizes, int n_in,
                              void* d_out, int out_size)
{
    const float* x  = (const float*)d_in[0];
    const float* rw = (const float*)d_in[1];
    const float* ew = (const float*)d_in[2];
    const float* eb = (const float*)d_in[3];
    float* out = (float*)d_out;

    const int full = (out_size >= BB * 2 + BB * EE + 1) ? 1 : 0;

    router_kernel<<<BB / 8, 256>>>(x, rw, out, full);
    compact_kernel<<<1, 1024>>>(out, full);
    expert_kernel<<<NBLK, 256>>>(x, ew, eb, out);
}